// round 9
// baseline (speedup 1.0000x reference)
#include <cuda_runtime.h>

#define NB    256
#define NS    64
#define KACT  8
#define INF_  1024
#define OUTF  1024
#define SUBF  128
#define QF    1024
#define NASG  (NB * KACT)      // 2048 total assignments (always exact)
#define KQ    8                // k-split of T across CTAs (128 i per CTA)
#define RPI   16               // rows per work item
#define MAXITEMS 192           // sum ceil(n_s/16) <= 128 + 64

// ---------------- device scratch (static globals: no runtime allocation) ----------
__device__ int   g_cnt[NS];
__device__ int   g_off[NS];
__device__ int   g_sel_s[NASG];
__device__ float g_sel_w[NASG];
__device__ int   g_asg_b[NASG];               // compacted: batch row per assignment
__device__ float g_asg_w[NASG];               // compacted: softmax weight per assignment
__device__ int   g_map[NASG];                 // (b,slot) -> compact index
__device__ int   g_work[MAXITEMS];            // (subnet<<8)|chunk
__device__ int   g_nwork;
__device__ unsigned g_done;                   // attn completion counter (self-resetting)
__device__ float g_Tpart[KQ * NASG * SUBF];   // stage-1 k-partials (raw sums), 8 MB
__device__ float g_T[(NASG + RPI) * SUBF];    // reduced, weight-applied (+pad rows)
__device__ float g_opart[NASG * OUTF];        // 8 MB partial outputs

// ---------------- cp.async helpers ------------------------------------------------
__device__ __forceinline__ void cp16(void* s, const void* g) {
    unsigned sa = (unsigned)__cvta_generic_to_shared(s);
    asm volatile("cp.async.cg.shared.global [%0], [%1], 16;\n" :: "r"(sa), "l"(g));
}
#define CP_COMMIT()  asm volatile("cp.async.commit_group;\n")
#define CP_WAIT(n)   asm volatile("cp.async.wait_group %0;\n" :: "n"(n))

__device__ __forceinline__ float4 f4add(float4 a, float4 b) {
    return make_float4(a.x + b.x, a.y + b.y, a.z + b.z, a.w + b.w);
}

// ---------------- kernel 1: attention + top-8 + softmax + (fused) scatter ---------
// 64 CTAs x 256 threads, 4 batch rows per CTA. Last CTA to finish runs the
// count/scan/compact/work-list stage (deterministic result regardless of order).
__global__ void __launch_bounds__(256) colak_attn(const float* __restrict__ q,
                                                  const float* __restrict__ Wk,
                                                  const float* __restrict__ bk) {
    __shared__ float qs[4 * QF];
    __shared__ float att[4][NS];
    const int b0   = blockIdx.x * 4;
    const int tid  = threadIdx.x;
    const int w    = tid >> 5;
    const int lane = tid & 31;

    for (int f = tid; f < 4 * (QF / 4); f += 256)
        ((float4*)qs)[f] = ((const float4*)(q + (size_t)b0 * QF))[f];
    __syncthreads();

    const float4* q4 = (const float4*)qs;
    #pragma unroll
    for (int p = 0; p < 8; p++) {
        const int s = p * 8 + w;
        const float4* wr = (const float4*)(Wk + (size_t)s * QF);
        float acc[4];
        #pragma unroll
        for (int r = 0; r < 4; r++) acc[r] = 0.f;
        #pragma unroll
        for (int i = lane; i < QF / 4; i += 32) {
            float4 a = wr[i];
            #pragma unroll
            for (int r = 0; r < 4; r++) {
                float4 c = q4[r * (QF / 4) + i];
                acc[r] += a.x * c.x + a.y * c.y + a.z * c.z + a.w * c.w;
            }
        }
        #pragma unroll
        for (int r = 0; r < 4; r++) {
            float v = acc[r];
            #pragma unroll
            for (int o = 16; o; o >>= 1) v += __shfl_xor_sync(0xffffffffu, v, o);
            if (lane == 0) att[r][s] = v + bk[s];
        }
    }
    __syncthreads();

    if (w < 4) {
        const int b = b0 + w;
        float v0 = att[w][lane], v1 = att[w][lane + 32];
        int r0 = 0, r1 = 0;
        #pragma unroll
        for (int j = 0; j < NS; j++) {
            float a = att[w][j];
            r0 += (a > v0) || (a == v0 && j < lane);
            r1 += (a > v1) || (a == v1 && j < lane + 32);
        }
        bool k0 = r0 < KACT, k1 = r1 < KACT;

        float m = fmaxf(k0 ? v0 : -1e30f, k1 ? v1 : -1e30f);
        #pragma unroll
        for (int o = 16; o; o >>= 1) m = fmaxf(m, __shfl_xor_sync(0xffffffffu, m, o));

        float e0 = k0 ? expf(v0 - m) : 0.f;
        float e1 = k1 ? expf(v1 - m) : 0.f;
        float sm = e0 + e1;
        #pragma unroll
        for (int o = 16; o; o >>= 1) sm += __shfl_xor_sync(0xffffffffu, sm, o);

        unsigned m0 = __ballot_sync(0xffffffffu, k0);
        unsigned m1 = __ballot_sync(0xffffffffu, k1);
        unsigned lt = (1u << lane) - 1u;
        int base1 = __popc(m0);
        if (k0) {
            int slot = __popc(m0 & lt);
            g_sel_s[b * KACT + slot] = lane;
            g_sel_w[b * KACT + slot] = e0 / sm;
        }
        if (k1) {
            int slot = base1 + __popc(m1 & lt);
            g_sel_s[b * KACT + slot] = lane + 32;
            g_sel_w[b * KACT + slot] = e1 / sm;
        }
    }

    // ---- last-CTA-done: run the scatter stage once all CTAs have written g_sel ----
    __shared__ int isLast;
    __syncthreads();
    if (tid == 0) {
        __threadfence();
        unsigned v = atomicAdd(&g_done, 1u);
        isLast = (v == gridDim.x - 1);
    }
    __syncthreads();
    if (!isLast) return;
    if (tid == 0) g_done = 0;   // reset for next graph replay
    __threadfence();

    __shared__ int cnt[NS], off_s[NS], fill[NS], ncoff[NS];
    if (tid < NS) cnt[tid] = 0;
    __syncthreads();
    for (int idx = tid; idx < NASG; idx += 256)
        atomicAdd(&cnt[g_sel_s[idx]], 1);
    __syncthreads();

    if (tid < 32) {
        int a = cnt[lane], b = cnt[lane + 32];
        int ia = a, ib = b;
        #pragma unroll
        for (int d = 1; d < 32; d <<= 1) {
            int t = __shfl_up_sync(0xffffffffu, ia, d); if (lane >= d) ia += t;
        }
        int tota = __shfl_sync(0xffffffffu, ia, 31);
        #pragma unroll
        for (int d = 1; d < 32; d <<= 1) {
            int t = __shfl_up_sync(0xffffffffu, ib, d); if (lane >= d) ib += t;
        }
        off_s[lane]      = ia - a;
        off_s[lane + 32] = tota + ib - b;

        int nca = (a + RPI - 1) / RPI, ncb = (b + RPI - 1) / RPI;
        int inca = nca, incb = ncb;
        #pragma unroll
        for (int d = 1; d < 32; d <<= 1) {
            int t = __shfl_up_sync(0xffffffffu, inca, d); if (lane >= d) inca += t;
        }
        int totnca = __shfl_sync(0xffffffffu, inca, 31);
        #pragma unroll
        for (int d = 1; d < 32; d <<= 1) {
            int t = __shfl_up_sync(0xffffffffu, incb, d); if (lane >= d) incb += t;
        }
        ncoff[lane]      = inca - nca;
        ncoff[lane + 32] = totnca + incb - ncb;
        if (lane == 31) g_nwork = totnca + incb;
    }
    __syncthreads();

    if (tid < NS) {
        g_cnt[tid] = cnt[tid]; g_off[tid] = off_s[tid]; fill[tid] = off_s[tid];
        int base = ncoff[tid];
        int nc = (cnt[tid] + RPI - 1) / RPI;
        for (int c = 0; c < nc; c++) g_work[base + c] = (tid << 8) | c;
    }
    __syncthreads();
    for (int idx = tid; idx < NASG; idx += 256) {
        int s = g_sel_s[idx];
        int p = atomicAdd(&fill[s], 1);
        g_asg_b[p] = idx >> 3;
        g_asg_w[p] = g_sel_w[idx];
        g_map[idx] = p;
    }
}

// ---------------- kernel T: stage 1 (k-eighth per CTA) ----------------------------
// CTA = (16 asg rows of one subnet, 128-wide i-slice). 128 threads, 4 warps.
// Warp w owns rows 4w..4w+3; thread owns 4r x 4j (j = 4*lane+cc). 16 acc regs.
// smem: V0 tile [128j][32i] swizzled db (32KB) + X [16r][32i] db (4KB) = 36KB.
#define V0TILE (128 * 32)
#define XTILE  (RPI * 32)
#define SMEM_T_BYTES ((2 * V0TILE + 2 * XTILE) * 4)
#define TKTILES 4     // 128 i per CTA / 32 per tile

__global__ void __launch_bounds__(128, 6) colak_T(const float* __restrict__ x,
                                                  const float* __restrict__ V0) {
    if ((int)blockIdx.x >= g_nwork) return;
    const int item = g_work[blockIdx.x];
    const int s  = item >> 8;
    const int c  = item & 255;
    const int kq = blockIdx.y;            // 0..KQ-1
    const int n  = g_cnt[s];
    const int m  = min(RPI, n - c * RPI);
    const int gbase = g_off[s] + c * RPI;

    extern __shared__ float smem[];
    float* V0s = smem;                    // 2 x [128][32]
    float* Xs  = smem + 2 * V0TILE;       // 2 x [16][32]
    __shared__ int rows[RPI];

    const int tid  = threadIdx.x;
    const int w    = tid >> 5;
    const int lane = tid & 31;
    const int r0   = w * 4;
    const int swz  = lane & 7;

    if (tid < RPI) rows[tid] = g_asg_b[gbase + min(tid, m - 1)];
    __syncthreads();

    const float* v0 = V0 + (size_t)s * SUBF * INF_;
    const int ibase = kq * 128;
    const int xr_ = tid >> 3;             // X staging: row 0..15
    const int vs_ = tid & 7;              // seg 0..7
    const float* xrow = x + (size_t)rows[xr_] * INF_;

    // prefetch tile 0
    {
        #pragma unroll
        for (int k = 0; k < 8; k++) {
            int idx = k * 128 + tid;
            int j = idx >> 3, seg = idx & 7;
            cp16(V0s + j * 32 + ((seg ^ ((j >> 2) & 7)) << 2),
                 v0 + (size_t)j * INF_ + ibase + seg * 4);
        }
        cp16(Xs + xr_ * 32 + vs_ * 4, xrow + ibase + vs_ * 4);
        CP_COMMIT();
    }

    float acc[4][4];
    #pragma unroll
    for (int r = 0; r < 4; r++)
        #pragma unroll
        for (int cc = 0; cc < 4; cc++) acc[r][cc] = 0.f;

    for (int t = 0; t < TKTILES; t++) {
        const float* Vb = V0s + (t & 1) * V0TILE;
        const float* Xb = Xs  + (t & 1) * XTILE;
        if (t + 1 < TKTILES) {
            const int i0 = ibase + (t + 1) * 32;
            float* vd = V0s + ((t + 1) & 1) * V0TILE;
            float* xd = Xs  + ((t + 1) & 1) * XTILE;
            #pragma unroll
            for (int k = 0; k < 8; k++) {
                int idx = k * 128 + tid;
                int j = idx >> 3, seg = idx & 7;
                cp16(vd + j * 32 + ((seg ^ ((j >> 2) & 7)) << 2),
                     v0 + (size_t)j * INF_ + i0 + seg * 4);
            }
            cp16(xd + xr_ * 32 + vs_ * 4, xrow + i0 + vs_ * 4);
            CP_COMMIT();
            CP_WAIT(1);
        } else {
            CP_WAIT(0);
        }
        __syncthreads();

        #pragma unroll
        for (int i4 = 0; i4 < 8; i4++) {
            float4 xv[4];
            #pragma unroll
            for (int r = 0; r < 4; r++)
                xv[r] = *(const float4*)(Xb + (r0 + r) * 32 + i4 * 4);   // broadcast
            const int i4s = (i4 ^ swz) << 2;
            #pragma unroll
            for (int cc = 0; cc < 4; cc++) {
                float4 v = *(const float4*)(Vb + (4 * lane + cc) * 32 + i4s);
                #pragma unroll
                for (int r = 0; r < 4; r++)
                    acc[r][cc] += v.x * xv[r].x + v.y * xv[r].y
                                + v.z * xv[r].z + v.w * xv[r].w;
            }
        }
        __syncthreads();   // all warps done with buf before next prefetch overwrites
    }

    float* dst = g_Tpart + (size_t)kq * NASG * SUBF;
    #pragma unroll
    for (int r = 0; r < 4; r++) {
        if (r0 + r < m) {
            float4 o = make_float4(acc[r][0], acc[r][1], acc[r][2], acc[r][3]);
            *(float4*)(dst + (size_t)(gbase + r0 + r) * SUBF + 4 * lane) = o;
        }
    }
}

// ---------------- kernel Tred: sum 8 k-partials, apply weight ---------------------
// All 8 loads issued before any arithmetic -> MLP=8, then pairwise tree sum.
__global__ void __launch_bounds__(256) colak_Tred() {
    const int idx = blockIdx.x * 256 + threadIdx.x;   // 0..65535
    const int row = idx >> 5, qd = idx & 31;
    const float4* base = (const float4*)g_Tpart + (size_t)row * 32 + qd;
    const size_t stride = (size_t)NASG * 32;

    float4 t0 = base[0];
    float4 t1 = base[stride];
    float4 t2 = base[2 * stride];
    float4 t3 = base[3 * stride];
    float4 t4 = base[4 * stride];
    float4 t5 = base[5 * stride];
    float4 t6 = base[6 * stride];
    float4 t7 = base[7 * stride];

    float4 s01 = f4add(t0, t1), s23 = f4add(t2, t3);
    float4 s45 = f4add(t4, t5), s67 = f4add(t6, t7);
    float4 s = f4add(f4add(s01, s23), f4add(s45, s67));

    const float wt = g_asg_w[row];
    s.x *= wt; s.y *= wt; s.z *= wt; s.w *= wt;
    *((float4*)g_T + (size_t)row * 32 + qd) = s;
}

// ---------------- kernel O: stage 2  O[r][o] = sum_j T[r][j]*V1[s][o][j] ----------
// CTA = (16 asg rows, 128-wide o-tile). 128 threads. k-tiles of 32 j, db cp.async.
// smem: V1 tile [128o][32j] swizzled db (32KB) + T [16r][32j] db (4KB) = 36KB.
#define V1TILE (128 * 32)
#define TTILE  (RPI * 32)
#define SMEM_O_BYTES ((2 * V1TILE + 2 * TTILE) * 4)

__global__ void __launch_bounds__(128, 6) colak_O(const float* __restrict__ V1) {
    if ((int)blockIdx.x >= g_nwork) return;
    const int item = g_work[blockIdx.x];
    const int s  = item >> 8;
    const int c  = item & 255;
    const int ot = blockIdx.y;            // 0..7
    const int n  = g_cnt[s];
    const int m  = min(RPI, n - c * RPI);
    const int gbase = g_off[s] + c * RPI;

    extern __shared__ float smem[];
    float* V1s = smem;                    // 2 x [128][32]
    float* Ts  = smem + 2 * V1TILE;       // 2 x [16][32]

    const int tid  = threadIdx.x;
    const int w    = tid >> 5;
    const int lane = tid & 31;
    const int r0   = w * 4;
    const int swz  = lane & 7;

    const float* v1 = V1 + (size_t)s * OUTF * SUBF + (size_t)ot * 128 * SUBF;
    const float* tsrc = g_T + (size_t)gbase * SUBF;
    const int xr_ = tid >> 3;
    const int vs_ = tid & 7;

    // prefetch tile 0 (j0 = 0)
    {
        #pragma unroll
        for (int k = 0; k < 8; k++) {
            int idx = k * 128 + tid;
            int o = idx >> 3, seg = idx & 7;
            cp16(V1s + o * 32 + ((seg ^ ((o >> 2) & 7)) << 2),
                 v1 + (size_t)o * SUBF + seg * 4);
        }
        cp16(Ts + xr_ * 32 + vs_ * 4, tsrc + (size_t)xr_ * SUBF + vs_ * 4);
        CP_COMMIT();
    }

    float acc[4][4];
    #pragma unroll
    for (int r = 0; r < 4; r++)
        #pragma unroll
        for (int cc = 0; cc < 4; cc++) acc[r][cc] = 0.f;

    for (int t = 0; t < 4; t++) {
        const float* Vb = V1s + (t & 1) * V1TILE;
        const float* Tb = Ts  + (t & 1) * TTILE;
        if (t + 1 < 4) {
            const int j0 = (t + 1) * 32;
            float* vd = V1s + ((t + 1) & 1) * V1TILE;
            float* td = Ts  + ((t + 1) & 1) * TTILE;
            #pragma unroll
            for (int k = 0; k < 8; k++) {
                int idx = k * 128 + tid;
                int o = idx >> 3, seg = idx & 7;
                cp16(vd + o * 32 + ((seg ^ ((o >> 2) & 7)) << 2),
                     v1 + (size_t)o * SUBF + j0 + seg * 4);
            }
            cp16(td + xr_ * 32 + vs_ * 4, tsrc + (size_t)xr_ * SUBF + j0 + vs_ * 4);
            CP_COMMIT();
            CP_WAIT(1);
        } else {
            CP_WAIT(0);
        }
        __syncthreads();

        #pragma unroll
        for (int j4 = 0; j4 < 8; j4++) {
            float4 tv[4];
            #pragma unroll
            for (int r = 0; r < 4; r++)
                tv[r] = *(const float4*)(Tb + (r0 + r) * 32 + j4 * 4);   // broadcast
            const int j4s = (j4 ^ swz) << 2;
            #pragma unroll
            for (int cc = 0; cc < 4; cc++) {
                float4 v = *(const float4*)(Vb + (4 * lane + cc) * 32 + j4s);
                #pragma unroll
                for (int r = 0; r < 4; r++)
                    acc[r][cc] += v.x * tv[r].x + v.y * tv[r].y
                                + v.z * tv[r].z + v.w * tv[r].w;
            }
        }
        __syncthreads();
    }

    #pragma unroll
    for (int r = 0; r < 4; r++) {
        if (r0 + r < m) {
            float4 o = make_float4(acc[r][0], acc[r][1], acc[r][2], acc[r][3]);
            *(float4*)(g_opart + (size_t)(gbase + r0 + r) * OUTF
                       + ot * 128 + 4 * lane) = o;
        }
    }
}

// ---------------- kernel 4: reduce 8 partials per batch row -----------------------
// All 8 gathered loads in flight before summation (MLP=8, tree sum).
__global__ void __launch_bounds__(256) colak_reduce(float* __restrict__ out) {
    __shared__ int mp[KACT];
    const int b = blockIdx.x;
    const int tid = threadIdx.x;
    if (tid < KACT) mp[tid] = g_map[b * KACT + tid];
    __syncthreads();
    const float4* op = (const float4*)g_opart;

    float4 t0 = op[(size_t)mp[0] * (OUTF / 4) + tid];
    float4 t1 = op[(size_t)mp[1] * (OUTF / 4) + tid];
    float4 t2 = op[(size_t)mp[2] * (OUTF / 4) + tid];
    float4 t3 = op[(size_t)mp[3] * (OUTF / 4) + tid];
    float4 t4 = op[(size_t)mp[4] * (OUTF / 4) + tid];
    float4 t5 = op[(size_t)mp[5] * (OUTF / 4) + tid];
    float4 t6 = op[(size_t)mp[6] * (OUTF / 4) + tid];
    float4 t7 = op[(size_t)mp[7] * (OUTF / 4) + tid];

    float4 s01 = f4add(t0, t1), s23 = f4add(t2, t3);
    float4 s45 = f4add(t4, t5), s67 = f4add(t6, t7);
    float4 s = f4add(f4add(s01, s23), f4add(s45, s67));

    ((float4*)out)[(size_t)b * (OUTF / 4) + tid] = s;
}

// ---------------- host launcher ----------------------------------------------------
extern "C" void kernel_launch(void* const* d_in, const int* in_sizes, int n_in,
                              void* d_out, int out_size) {
    const float* x  = (const float*)d_in[0];
    const float* q  = (const float*)d_in[1];
    const float* Wk = (const float*)d_in[2];
    const float* bk = (const float*)d_in[3];
    const float* V0 = (const float*)d_in[4];
    const float* V1 = (const float*)d_in[5];
    float* out = (float*)d_out;

    colak_attn<<<NB / 4, 256>>>(q, Wk, bk);
    colak_T<<<dim3(MAXITEMS, KQ), 128, SMEM_T_BYTES>>>(x, V0);
    colak_Tred<<<NASG * SUBF / (256 * 4), 256>>>();
    colak_O<<<dim3(MAXITEMS, 8), 128, SMEM_O_BYTES>>>(V1);
    colak_reduce<<<NB, 256>>>(out);
}

// round 10
// speedup vs baseline: 1.4086x; 1.4086x over previous
#include <cuda_runtime.h>

#define NB    256
#define NS    64
#define KACT  8
#define INF_  1024
#define OUTF  1024
#define SUBF  128
#define QF    1024
#define NASG  (NB * KACT)      // 2048 total assignments (always exact)
#define KQ    8                // k-split of T across CTAs (128 i per CTA)
#define RPI   16               // rows per work item
#define MAXITEMS 192           // sum ceil(n_s/16) <= 128 + 64
#define VSTR  36               // smem row pitch (floats): conflict-free, 16B-aligned

// ---------------- device scratch (static globals: no runtime allocation) ----------
__device__ int   g_cnt[NS];
__device__ int   g_off[NS];
__device__ int   g_sel_s[NASG];
__device__ float g_sel_w[NASG];
__device__ int   g_asg_b[NASG];               // compacted: batch row per assignment
__device__ float g_asg_w[NASG];               // compacted: softmax weight per assignment
__device__ int   g_map[NASG];                 // (b,slot) -> compact index
__device__ int   g_work[MAXITEMS];            // (subnet<<8)|chunk
__device__ int   g_nwork;
__device__ float g_Tpart[KQ * NASG * SUBF];   // stage-1 k-partials (raw sums), 8 MB
__device__ float g_T[(NASG + RPI) * SUBF];    // reduced, weight-applied (+pad rows)
__device__ float g_opart[NASG * OUTF];        // 8 MB partial outputs

// ---------------- helpers -----------------------------------------------------------
__device__ __forceinline__ void cp16(void* s, const void* g) {
    unsigned sa = (unsigned)__cvta_generic_to_shared(s);
    asm volatile("cp.async.cg.shared.global [%0], [%1], 16;\n" :: "r"(sa), "l"(g));
}
#define CP_COMMIT()  asm volatile("cp.async.commit_group;\n")
#define CP_WAIT(n)   asm volatile("cp.async.wait_group %0;\n" :: "n"(n))

__device__ __forceinline__ float4 f4add(float4 a, float4 b) {
    return make_float4(a.x + b.x, a.y + b.y, a.z + b.z, a.w + b.w);
}
__device__ __forceinline__ unsigned f2tf(float f) {
    unsigned r; asm("cvt.rna.tf32.f32 %0, %1;" : "=r"(r) : "f"(f)); return r;
}
__device__ __forceinline__ void mma_tf32(float* c, unsigned a0, unsigned a1,
                                         unsigned a2, unsigned a3,
                                         unsigned b0, unsigned b1) {
    asm volatile(
        "mma.sync.aligned.m16n8k8.row.col.f32.tf32.tf32.f32 "
        "{%0,%1,%2,%3}, {%4,%5,%6,%7}, {%8,%9}, {%0,%1,%2,%3};"
        : "+f"(c[0]), "+f"(c[1]), "+f"(c[2]), "+f"(c[3])
        : "r"(a0), "r"(a1), "r"(a2), "r"(a3), "r"(b0), "r"(b1));
}

// ---------------- kernel 1: attention + top-8 + softmax ---------------------------
// 64 CTAs x 256 threads, 4 batch rows per CTA.
__global__ void __launch_bounds__(256) colak_attn(const float* __restrict__ q,
                                                  const float* __restrict__ Wk,
                                                  const float* __restrict__ bk) {
    __shared__ float qs[4 * QF];
    __shared__ float att[4][NS];
    const int b0   = blockIdx.x * 4;
    const int tid  = threadIdx.x;
    const int w    = tid >> 5;
    const int lane = tid & 31;

    for (int f = tid; f < 4 * (QF / 4); f += 256)
        ((float4*)qs)[f] = ((const float4*)(q + (size_t)b0 * QF))[f];
    __syncthreads();

    const float4* q4 = (const float4*)qs;
    #pragma unroll
    for (int p = 0; p < 8; p++) {
        const int s = p * 8 + w;
        const float4* wr = (const float4*)(Wk + (size_t)s * QF);
        float acc[4];
        #pragma unroll
        for (int r = 0; r < 4; r++) acc[r] = 0.f;
        #pragma unroll
        for (int i = lane; i < QF / 4; i += 32) {
            float4 a = wr[i];
            #pragma unroll
            for (int r = 0; r < 4; r++) {
                float4 c = q4[r * (QF / 4) + i];
                acc[r] += a.x * c.x + a.y * c.y + a.z * c.z + a.w * c.w;
            }
        }
        #pragma unroll
        for (int r = 0; r < 4; r++) {
            float v = acc[r];
            #pragma unroll
            for (int o = 16; o; o >>= 1) v += __shfl_xor_sync(0xffffffffu, v, o);
            if (lane == 0) att[r][s] = v + bk[s];
        }
    }
    __syncthreads();

    if (w < 4) {
        const int b = b0 + w;
        float v0 = att[w][lane], v1 = att[w][lane + 32];
        int r0 = 0, r1 = 0;
        #pragma unroll
        for (int j = 0; j < NS; j++) {
            float a = att[w][j];
            r0 += (a > v0) || (a == v0 && j < lane);
            r1 += (a > v1) || (a == v1 && j < lane + 32);
        }
        bool k0 = r0 < KACT, k1 = r1 < KACT;

        float m = fmaxf(k0 ? v0 : -1e30f, k1 ? v1 : -1e30f);
        #pragma unroll
        for (int o = 16; o; o >>= 1) m = fmaxf(m, __shfl_xor_sync(0xffffffffu, m, o));

        float e0 = k0 ? expf(v0 - m) : 0.f;
        float e1 = k1 ? expf(v1 - m) : 0.f;
        float sm = e0 + e1;
        #pragma unroll
        for (int o = 16; o; o >>= 1) sm += __shfl_xor_sync(0xffffffffu, sm, o);

        unsigned m0 = __ballot_sync(0xffffffffu, k0);
        unsigned m1 = __ballot_sync(0xffffffffu, k1);
        unsigned lt = (1u << lane) - 1u;
        int base1 = __popc(m0);
        if (k0) {
            int slot = __popc(m0 & lt);
            g_sel_s[b * KACT + slot] = lane;
            g_sel_w[b * KACT + slot] = e0 / sm;
        }
        if (k1) {
            int slot = base1 + __popc(m1 & lt);
            g_sel_s[b * KACT + slot] = lane + 32;
            g_sel_w[b * KACT + slot] = e1 / sm;
        }
    }
}

// ---------------- kernel 2: count + scans + compact + work list (one block) -------
__global__ void __launch_bounds__(256) colak_scatter() {
    __shared__ int cnt[NS], off_s[NS], fill[NS], ncoff[NS];
    const int tid = threadIdx.x;
    const int lane = tid & 31;
    if (tid < NS) cnt[tid] = 0;
    __syncthreads();
    for (int idx = tid; idx < NASG; idx += 256)
        atomicAdd(&cnt[g_sel_s[idx]], 1);
    __syncthreads();

    if (tid < 32) {
        int a = cnt[lane], b = cnt[lane + 32];
        int ia = a, ib = b;
        #pragma unroll
        for (int d = 1; d < 32; d <<= 1) {
            int t = __shfl_up_sync(0xffffffffu, ia, d); if (lane >= d) ia += t;
        }
        int tota = __shfl_sync(0xffffffffu, ia, 31);
        #pragma unroll
        for (int d = 1; d < 32; d <<= 1) {
            int t = __shfl_up_sync(0xffffffffu, ib, d); if (lane >= d) ib += t;
        }
        off_s[lane]      = ia - a;
        off_s[lane + 32] = tota + ib - b;

        int nca = (a + RPI - 1) / RPI, ncb = (b + RPI - 1) / RPI;
        int inca = nca, incb = ncb;
        #pragma unroll
        for (int d = 1; d < 32; d <<= 1) {
            int t = __shfl_up_sync(0xffffffffu, inca, d); if (lane >= d) inca += t;
        }
        int totnca = __shfl_sync(0xffffffffu, inca, 31);
        #pragma unroll
        for (int d = 1; d < 32; d <<= 1) {
            int t = __shfl_up_sync(0xffffffffu, incb, d); if (lane >= d) incb += t;
        }
        ncoff[lane]      = inca - nca;
        ncoff[lane + 32] = totnca + incb - ncb;
        if (lane == 31) g_nwork = totnca + incb;
    }
    __syncthreads();

    if (tid < NS) {
        g_cnt[tid] = cnt[tid]; g_off[tid] = off_s[tid]; fill[tid] = off_s[tid];
        int base = ncoff[tid];
        int nc = (cnt[tid] + RPI - 1) / RPI;
        for (int c = 0; c < nc; c++) g_work[base + c] = (tid << 8) | c;
    }
    __syncthreads();
    for (int idx = tid; idx < NASG; idx += 256) {
        int s = g_sel_s[idx];
        int p = atomicAdd(&fill[s], 1);
        g_asg_b[p] = idx >> 3;
        g_asg_w[p] = g_sel_w[idx];
        g_map[idx] = p;
    }
}

// ---------------- kernel T: stage 1 via tf32 mma -----------------------------------
// CTA = (16 asg rows of one subnet, 128-wide i-slice). 128 threads, 4 warps.
// Warp w owns the 32-wide j-slice [32w, 32w+32). Each warp: M=16, N=32, K=128
// as m16n8k8 tf32 MMAs (4 n-tiles x 16 k-steps over 4 staged k-tiles).
// smem: V0 tile [128j][32i]@pitch36 db + X [16r][32i]@pitch36 db = 40.5 KB.
#define SMEM_MMA_BYTES ((2 * 128 * VSTR + 2 * RPI * VSTR) * 4)

__global__ void __launch_bounds__(128) colak_T(const float* __restrict__ x,
                                               const float* __restrict__ V0) {
    if ((int)blockIdx.x >= g_nwork) return;
    const int item = g_work[blockIdx.x];
    const int s  = item >> 8;
    const int c  = item & 255;
    const int kq = blockIdx.y;            // 0..KQ-1
    const int n  = g_cnt[s];
    const int m  = min(RPI, n - c * RPI);
    const int gbase = g_off[s] + c * RPI;

    extern __shared__ float smem[];
    float* Vb0 = smem;                    // 2 x [128][VSTR]
    float* Xb0 = smem + 2 * 128 * VSTR;   // 2 x [16][VSTR]
    __shared__ int rows[RPI];

    const int tid  = threadIdx.x;
    const int w    = tid >> 5;
    const int lane = tid & 31;
    const int lr   = lane >> 2;           // 0..7
    const int lc   = lane & 3;            // 0..3
    const int jb   = w * 32;

    if (tid < RPI) rows[tid] = g_asg_b[gbase + min(tid, m - 1)];
    __syncthreads();

    const float* v0 = V0 + (size_t)s * SUBF * INF_;
    const int ibase = kq * 128;
    const int sr = tid >> 3, ss = tid & 7;
    const float* xrow = x + (size_t)rows[sr] * INF_;

    // prefetch tile 0
    {
        #pragma unroll
        for (int k = 0; k < 8; k++) {
            int idx = k * 128 + tid, j = idx >> 3, seg = idx & 7;
            cp16(Vb0 + j * VSTR + seg * 4, v0 + (size_t)j * INF_ + ibase + seg * 4);
        }
        cp16(Xb0 + sr * VSTR + ss * 4, xrow + ibase + ss * 4);
        CP_COMMIT();
    }

    float acc[4][4];
    #pragma unroll
    for (int nt = 0; nt < 4; nt++)
        #pragma unroll
        for (int i = 0; i < 4; i++) acc[nt][i] = 0.f;

    for (int t = 0; t < 4; t++) {
        const float* Vb = Vb0 + (t & 1) * 128 * VSTR;
        const float* Xb = Xb0 + (t & 1) * RPI * VSTR;
        if (t + 1 < 4) {
            const int i0 = ibase + (t + 1) * 32;
            float* vd = Vb0 + ((t + 1) & 1) * 128 * VSTR;
            float* xd = Xb0 + ((t + 1) & 1) * RPI * VSTR;
            #pragma unroll
            for (int k = 0; k < 8; k++) {
                int idx = k * 128 + tid, j = idx >> 3, seg = idx & 7;
                cp16(vd + j * VSTR + seg * 4, v0 + (size_t)j * INF_ + i0 + seg * 4);
            }
            cp16(xd + sr * VSTR + ss * 4, xrow + i0 + ss * 4);
            CP_COMMIT();
            CP_WAIT(1);
        } else {
            CP_WAIT(0);
        }
        __syncthreads();

        #pragma unroll
        for (int ks = 0; ks < 4; ks++) {
            const int kk = ks * 8;
            unsigned a0 = f2tf(Xb[lr * VSTR + kk + lc]);
            unsigned a1 = f2tf(Xb[(lr + 8) * VSTR + kk + lc]);
            unsigned a2 = f2tf(Xb[lr * VSTR + kk + lc + 4]);
            unsigned a3 = f2tf(Xb[(lr + 8) * VSTR + kk + lc + 4]);
            #pragma unroll
            for (int nt = 0; nt < 4; nt++) {
                const int nn = jb + nt * 8 + lr;
                unsigned b0 = f2tf(Vb[nn * VSTR + kk + lc]);
                unsigned b1 = f2tf(Vb[nn * VSTR + kk + lc + 4]);
                mma_tf32(acc[nt], a0, a1, a2, a3, b0, b1);
            }
        }
        __syncthreads();
    }

    float* dst = g_Tpart + (size_t)kq * NASG * SUBF;
    #pragma unroll
    for (int nt = 0; nt < 4; nt++) {
        const int col = jb + nt * 8 + 2 * lc;
        if (lr < m)
            *(float2*)(dst + (size_t)(gbase + lr) * SUBF + col)
                = make_float2(acc[nt][0], acc[nt][1]);
        if (lr + 8 < m)
            *(float2*)(dst + (size_t)(gbase + lr + 8) * SUBF + col)
                = make_float2(acc[nt][2], acc[nt][3]);
    }
}

// ---------------- kernel Tred: sum 8 k-partials, apply weight (MLP=8) -------------
__global__ void __launch_bounds__(256) colak_Tred() {
    const int idx = blockIdx.x * 256 + threadIdx.x;   // 0..65535
    const int row = idx >> 5, qd = idx & 31;
    const float4* base = (const float4*)g_Tpart + (size_t)row * 32 + qd;
    const size_t stride = (size_t)NASG * 32;

    float4 t0 = base[0];
    float4 t1 = base[stride];
    float4 t2 = base[2 * stride];
    float4 t3 = base[3 * stride];
    float4 t4 = base[4 * stride];
    float4 t5 = base[5 * stride];
    float4 t6 = base[6 * stride];
    float4 t7 = base[7 * stride];

    float4 s = f4add(f4add(f4add(t0, t1), f4add(t2, t3)),
                     f4add(f4add(t4, t5), f4add(t6, t7)));
    const float wt = g_asg_w[row];
    s.x *= wt; s.y *= wt; s.z *= wt; s.w *= wt;
    *((float4*)g_T + (size_t)row * 32 + qd) = s;
}

// ---------------- kernel O: stage 2 via tf32 mma -----------------------------------
// CTA = (16 asg rows, 128-wide o-tile). Same MMA structure as colak_T with
// A = T rows (K=128 j), B = V1 o-rows.
__global__ void __launch_bounds__(128) colak_O(const float* __restrict__ V1) {
    if ((int)blockIdx.x >= g_nwork) return;
    const int item = g_work[blockIdx.x];
    const int s  = item >> 8;
    const int c  = item & 255;
    const int ot = blockIdx.y;            // 0..7
    const int n  = g_cnt[s];
    const int m  = min(RPI, n - c * RPI);
    const int gbase = g_off[s] + c * RPI;

    extern __shared__ float smem[];
    float* Vb0 = smem;                    // 2 x [128][VSTR]
    float* Tb0 = smem + 2 * 128 * VSTR;   // 2 x [16][VSTR]

    const int tid  = threadIdx.x;
    const int w    = tid >> 5;
    const int lane = tid & 31;
    const int lr   = lane >> 2;
    const int lc   = lane & 3;
    const int ob   = w * 32;

    const float* v1 = V1 + (size_t)s * OUTF * SUBF + (size_t)ot * 128 * SUBF;
    const float* tsrc = g_T + (size_t)gbase * SUBF;
    const int sr = tid >> 3, ss = tid & 7;

    // prefetch tile 0 (j0 = 0)
    {
        #pragma unroll
        for (int k = 0; k < 8; k++) {
            int idx = k * 128 + tid, o = idx >> 3, seg = idx & 7;
            cp16(Vb0 + o * VSTR + seg * 4, v1 + (size_t)o * SUBF + seg * 4);
        }
        cp16(Tb0 + sr * VSTR + ss * 4, tsrc + (size_t)sr * SUBF + ss * 4);
        CP_COMMIT();
    }

    float acc[4][4];
    #pragma unroll
    for (int nt = 0; nt < 4; nt++)
        #pragma unroll
        for (int i = 0; i < 4; i++) acc[nt][i] = 0.f;

    for (int t = 0; t < 4; t++) {
        const float* Vb = Vb0 + (t & 1) * 128 * VSTR;
        const float* Tb = Tb0 + (t & 1) * RPI * VSTR;
        if (t + 1 < 4) {
            const int j0 = (t + 1) * 32;
            float* vd = Vb0 + ((t + 1) & 1) * 128 * VSTR;
            float* td = Tb0 + ((t + 1) & 1) * RPI * VSTR;
            #pragma unroll
            for (int k = 0; k < 8; k++) {
                int idx = k * 128 + tid, o = idx >> 3, seg = idx & 7;
                cp16(vd + o * VSTR + seg * 4, v1 + (size_t)o * SUBF + j0 + seg * 4);
            }
            cp16(td + sr * VSTR + ss * 4, tsrc + (size_t)sr * SUBF + j0 + ss * 4);
            CP_COMMIT();
            CP_WAIT(1);
        } else {
            CP_WAIT(0);
        }
        __syncthreads();

        #pragma unroll
        for (int ks = 0; ks < 4; ks++) {
            const int kk = ks * 8;
            unsigned a0 = f2tf(Tb[lr * VSTR + kk + lc]);
            unsigned a1 = f2tf(Tb[(lr + 8) * VSTR + kk + lc]);
            unsigned a2 = f2tf(Tb[lr * VSTR + kk + lc + 4]);
            unsigned a3 = f2tf(Tb[(lr + 8) * VSTR + kk + lc + 4]);
            #pragma unroll
            for (int nt = 0; nt < 4; nt++) {
                const int nn = ob + nt * 8 + lr;
                unsigned b0 = f2tf(Vb[nn * VSTR + kk + lc]);
                unsigned b1 = f2tf(Vb[nn * VSTR + kk + lc + 4]);
                mma_tf32(acc[nt], a0, a1, a2, a3, b0, b1);
            }
        }
        __syncthreads();
    }

    #pragma unroll
    for (int nt = 0; nt < 4; nt++) {
        const int col = ot * 128 + ob + nt * 8 + 2 * lc;
        if (lr < m)
            *(float2*)(g_opart + (size_t)(gbase + lr) * OUTF + col)
                = make_float2(acc[nt][0], acc[nt][1]);
        if (lr + 8 < m)
            *(float2*)(g_opart + (size_t)(gbase + lr + 8) * OUTF + col)
                = make_float2(acc[nt][2], acc[nt][3]);
    }
}

// ---------------- kernel 4: reduce 8 partials per batch row (MLP=8) ---------------
__global__ void __launch_bounds__(256) colak_reduce(float* __restrict__ out) {
    __shared__ int mp[KACT];
    const int b = blockIdx.x;
    const int tid = threadIdx.x;
    if (tid < KACT) mp[tid] = g_map[b * KACT + tid];
    __syncthreads();
    const float4* op = (const float4*)g_opart;

    float4 t0 = op[(size_t)mp[0] * (OUTF / 4) + tid];
    float4 t1 = op[(size_t)mp[1] * (OUTF / 4) + tid];
    float4 t2 = op[(size_t)mp[2] * (OUTF / 4) + tid];
    float4 t3 = op[(size_t)mp[3] * (OUTF / 4) + tid];
    float4 t4 = op[(size_t)mp[4] * (OUTF / 4) + tid];
    float4 t5 = op[(size_t)mp[5] * (OUTF / 4) + tid];
    float4 t6 = op[(size_t)mp[6] * (OUTF / 4) + tid];
    float4 t7 = op[(size_t)mp[7] * (OUTF / 4) + tid];

    float4 s = f4add(f4add(f4add(t0, t1), f4add(t2, t3)),
                     f4add(f4add(t4, t5), f4add(t6, t7)));
    ((float4*)out)[(size_t)b * (OUTF / 4) + tid] = s;
}

// ---------------- host launcher ----------------------------------------------------
extern "C" void kernel_launch(void* const* d_in, const int* in_sizes, int n_in,
                              void* d_out, int out_size) {
    const float* x  = (const float*)d_in[0];
    const float* q  = (const float*)d_in[1];
    const float* Wk = (const float*)d_in[2];
    const float* bk = (const float*)d_in[3];
    const float* V0 = (const float*)d_in[4];
    const float* V1 = (const float*)d_in[5];
    float* out = (float*)d_out;

    colak_attn<<<NB / 4, 256>>>(q, Wk, bk);
    colak_scatter<<<1, 256>>>();
    colak_T<<<dim3(MAXITEMS, KQ), 128, SMEM_MMA_BYTES>>>(x, V0);
    colak_Tred<<<NASG * SUBF / (256 * 4), 256>>>();
    colak_O<<<dim3(MAXITEMS, 8), 128, SMEM_MMA_BYTES>>>(V1);
    colak_reduce<<<NB, 256>>>(out);
}

// round 11
// speedup vs baseline: 1.5013x; 1.0658x over previous
#include <cuda_runtime.h>

#define NB    256
#define NS    64
#define KACT  8
#define INF_  1024
#define OUTF  1024
#define SUBF  128
#define QF    1024
#define NASG  (NB * KACT)      // 2048 total assignments (always exact)
#define KQ    8                // k-split of T across CTAs (128 i per CTA)
#define RPI   32               // rows per work item
#define MAXITEMS 128           // sum ceil(n_s/32) <= 64 + 64
#define VSTR  36               // smem row pitch (floats): conflict-free, 16B-aligned

// ---------------- device scratch (static globals: no runtime allocation) ----------
__device__ int   g_cnt[NS];
__device__ int   g_off[NS];
__device__ int   g_sel_s[NASG];
__device__ float g_sel_w[NASG];
__device__ int   g_asg_b[NASG];               // compacted: batch row per assignment
__device__ float g_asg_w[NASG];               // compacted: softmax weight per assignment
__device__ int   g_map[NASG];                 // (b,slot) -> compact index
__device__ int   g_work[MAXITEMS];            // (subnet<<8)|chunk
__device__ int   g_nwork;
__device__ float g_Tpart[NASG * KQ * SUBF];   // stage-1 k-partials, layout [row][kq][col]
__device__ float g_T[(NASG + RPI) * SUBF];    // reduced, weight-applied (+pad rows)
__device__ float g_opart[NASG * OUTF];        // 8 MB partial outputs

// ---------------- helpers -----------------------------------------------------------
__device__ __forceinline__ void cp16(void* s, const void* g) {
    unsigned sa = (unsigned)__cvta_generic_to_shared(s);
    asm volatile("cp.async.cg.shared.global [%0], [%1], 16;\n" :: "r"(sa), "l"(g));
}
#define CP_COMMIT()  asm volatile("cp.async.commit_group;\n")
#define CP_WAIT(n)   asm volatile("cp.async.wait_group %0;\n" :: "n"(n))

__device__ __forceinline__ float4 f4add(float4 a, float4 b) {
    return make_float4(a.x + b.x, a.y + b.y, a.z + b.z, a.w + b.w);
}
__device__ __forceinline__ unsigned f2tf(float f) {
    unsigned r; asm("cvt.rna.tf32.f32 %0, %1;" : "=r"(r) : "f"(f)); return r;
}
__device__ __forceinline__ void mma_tf32(float* c, unsigned a0, unsigned a1,
                                         unsigned a2, unsigned a3,
                                         unsigned b0, unsigned b1) {
    asm volatile(
        "mma.sync.aligned.m16n8k8.row.col.f32.tf32.tf32.f32 "
        "{%0,%1,%2,%3}, {%4,%5,%6,%7}, {%8,%9}, {%0,%1,%2,%3};"
        : "+f"(c[0]), "+f"(c[1]), "+f"(c[2]), "+f"(c[3])
        : "r"(a0), "r"(a1), "r"(a2), "r"(a3), "r"(b0), "r"(b1));
}

// ---------------- kernel 1: attention + top-8 + softmax ---------------------------
// 64 CTAs x 256 threads, 4 batch rows per CTA.
__global__ void __launch_bounds__(256) colak_attn(const float* __restrict__ q,
                                                  const float* __restrict__ Wk,
                                                  const float* __restrict__ bk) {
    __shared__ float qs[4 * QF];
    __shared__ float att[4][NS];
    const int b0   = blockIdx.x * 4;
    const int tid  = threadIdx.x;
    const int w    = tid >> 5;
    const int lane = tid & 31;

    for (int f = tid; f < 4 * (QF / 4); f += 256)
        ((float4*)qs)[f] = ((const float4*)(q + (size_t)b0 * QF))[f];
    __syncthreads();

    const float4* q4 = (const float4*)qs;
    #pragma unroll
    for (int p = 0; p < 8; p++) {
        const int s = p * 8 + w;
        const float4* wr = (const float4*)(Wk + (size_t)s * QF);
        float acc[4];
        #pragma unroll
        for (int r = 0; r < 4; r++) acc[r] = 0.f;
        #pragma unroll
        for (int i = lane; i < QF / 4; i += 32) {
            float4 a = wr[i];
            #pragma unroll
            for (int r = 0; r < 4; r++) {
                float4 c = q4[r * (QF / 4) + i];
                acc[r] += a.x * c.x + a.y * c.y + a.z * c.z + a.w * c.w;
            }
        }
        #pragma unroll
        for (int r = 0; r < 4; r++) {
            float v = acc[r];
            #pragma unroll
            for (int o = 16; o; o >>= 1) v += __shfl_xor_sync(0xffffffffu, v, o);
            if (lane == 0) att[r][s] = v + bk[s];
        }
    }
    __syncthreads();

    if (w < 4) {
        const int b = b0 + w;
        float v0 = att[w][lane], v1 = att[w][lane + 32];
        int r0 = 0, r1 = 0;
        #pragma unroll
        for (int j = 0; j < NS; j++) {
            float a = att[w][j];
            r0 += (a > v0) || (a == v0 && j < lane);
            r1 += (a > v1) || (a == v1 && j < lane + 32);
        }
        bool k0 = r0 < KACT, k1 = r1 < KACT;

        float m = fmaxf(k0 ? v0 : -1e30f, k1 ? v1 : -1e30f);
        #pragma unroll
        for (int o = 16; o; o >>= 1) m = fmaxf(m, __shfl_xor_sync(0xffffffffu, m, o));

        float e0 = k0 ? expf(v0 - m) : 0.f;
        float e1 = k1 ? expf(v1 - m) : 0.f;
        float sm = e0 + e1;
        #pragma unroll
        for (int o = 16; o; o >>= 1) sm += __shfl_xor_sync(0xffffffffu, sm, o);

        unsigned m0 = __ballot_sync(0xffffffffu, k0);
        unsigned m1 = __ballot_sync(0xffffffffu, k1);
        unsigned lt = (1u << lane) - 1u;
        int base1 = __popc(m0);
        if (k0) {
            int slot = __popc(m0 & lt);
            g_sel_s[b * KACT + slot] = lane;
            g_sel_w[b * KACT + slot] = e0 / sm;
        }
        if (k1) {
            int slot = base1 + __popc(m1 & lt);
            g_sel_s[b * KACT + slot] = lane + 32;
            g_sel_w[b * KACT + slot] = e1 / sm;
        }
    }
}

// ---------------- kernel 2: count + scans + compact + work list (one block) -------
__global__ void __launch_bounds__(256) colak_scatter() {
    __shared__ int cnt[NS], off_s[NS], fill[NS], ncoff[NS];
    const int tid = threadIdx.x;
    const int lane = tid & 31;
    if (tid < NS) cnt[tid] = 0;
    __syncthreads();
    for (int idx = tid; idx < NASG; idx += 256)
        atomicAdd(&cnt[g_sel_s[idx]], 1);
    __syncthreads();

    if (tid < 32) {
        int a = cnt[lane], b = cnt[lane + 32];
        int ia = a, ib = b;
        #pragma unroll
        for (int d = 1; d < 32; d <<= 1) {
            int t = __shfl_up_sync(0xffffffffu, ia, d); if (lane >= d) ia += t;
        }
        int tota = __shfl_sync(0xffffffffu, ia, 31);
        #pragma unroll
        for (int d = 1; d < 32; d <<= 1) {
            int t = __shfl_up_sync(0xffffffffu, ib, d); if (lane >= d) ib += t;
        }
        off_s[lane]      = ia - a;
        off_s[lane + 32] = tota + ib - b;

        int nca = (a + RPI - 1) / RPI, ncb = (b + RPI - 1) / RPI;
        int inca = nca, incb = ncb;
        #pragma unroll
        for (int d = 1; d < 32; d <<= 1) {
            int t = __shfl_up_sync(0xffffffffu, inca, d); if (lane >= d) inca += t;
        }
        int totnca = __shfl_sync(0xffffffffu, inca, 31);
        #pragma unroll
        for (int d = 1; d < 32; d <<= 1) {
            int t = __shfl_up_sync(0xffffffffu, incb, d); if (lane >= d) incb += t;
        }
        ncoff[lane]      = inca - nca;
        ncoff[lane + 32] = totnca + incb - ncb;
        if (lane == 31) g_nwork = totnca + incb;
    }
    __syncthreads();

    if (tid < NS) {
        g_cnt[tid] = cnt[tid]; g_off[tid] = off_s[tid]; fill[tid] = off_s[tid];
        int base = ncoff[tid];
        int nc = (cnt[tid] + RPI - 1) / RPI;
        for (int c = 0; c < nc; c++) g_work[base + c] = (tid << 8) | c;
    }
    __syncthreads();
    for (int idx = tid; idx < NASG; idx += 256) {
        int s = g_sel_s[idx];
        int p = atomicAdd(&fill[s], 1);
        g_asg_b[p] = idx >> 3;
        g_asg_w[p] = g_sel_w[idx];
        g_map[idx] = p;
    }
}

// ---------------- kernel T: stage 1 via tf32 mma (M=32 per CTA) --------------------
// CTA = (32 asg rows of one subnet, 128-wide i-slice). 128 threads, 4 warps.
// Warp w: M=32 (2 m-tiles) x N=32 (4 n-tiles), K=128 over 4 staged k-tiles.
// Per k8-step: 8 A-LDS+CVT, 8 B-LDS+CVT (reused by 2 m-tiles), 8 MMA = 5 instr/MMA.
// smem: V0 [128j][32i]@36 db + X [32r][32i]@36 db = 45 KB (fits 48KB default).
#define SMEM_MMA_BYTES ((2 * 128 * VSTR + 2 * RPI * VSTR) * 4)

__global__ void __launch_bounds__(128) colak_T(const float* __restrict__ x,
                                               const float* __restrict__ V0) {
    if ((int)blockIdx.x >= g_nwork) return;
    const int item = g_work[blockIdx.x];
    const int s  = item >> 8;
    const int c  = item & 255;
    const int kq = blockIdx.y;            // 0..KQ-1
    const int n  = g_cnt[s];
    const int m  = min(RPI, n - c * RPI);
    const int gbase = g_off[s] + c * RPI;

    extern __shared__ float smem[];
    float* Vb0 = smem;                    // 2 x [128][VSTR]
    float* Xb0 = smem + 2 * 128 * VSTR;   // 2 x [32][VSTR]
    __shared__ int rows[RPI];

    const int tid  = threadIdx.x;
    const int w    = tid >> 5;
    const int lane = tid & 31;
    const int lr   = lane >> 2;           // 0..7
    const int lc   = lane & 3;            // 0..3
    const int jb   = w * 32;

    if (tid < RPI) rows[tid] = g_asg_b[gbase + min(tid, m - 1)];
    __syncthreads();

    const float* v0 = V0 + (size_t)s * SUBF * INF_;
    const int ibase = kq * 128;
    const int sr = tid >> 3, ss = tid & 7;     // staging: rows sr and sr+16, seg ss
    const float* xrow0 = x + (size_t)rows[sr] * INF_;
    const float* xrow1 = x + (size_t)rows[sr + 16] * INF_;

    // prefetch tile 0
    {
        #pragma unroll
        for (int k = 0; k < 8; k++) {
            int idx = k * 128 + tid, j = idx >> 3, seg = idx & 7;
            cp16(Vb0 + j * VSTR + seg * 4, v0 + (size_t)j * INF_ + ibase + seg * 4);
        }
        cp16(Xb0 + sr * VSTR + ss * 4, xrow0 + ibase + ss * 4);
        cp16(Xb0 + (sr + 16) * VSTR + ss * 4, xrow1 + ibase + ss * 4);
        CP_COMMIT();
    }

    float acc[2][4][4];
    #pragma unroll
    for (int mt = 0; mt < 2; mt++)
        #pragma unroll
        for (int nt = 0; nt < 4; nt++)
            #pragma unroll
            for (int i = 0; i < 4; i++) acc[mt][nt][i] = 0.f;

    for (int t = 0; t < 4; t++) {
        const float* Vb = Vb0 + (t & 1) * 128 * VSTR;
        const float* Xb = Xb0 + (t & 1) * RPI * VSTR;
        if (t + 1 < 4) {
            const int i0 = ibase + (t + 1) * 32;
            float* vd = Vb0 + ((t + 1) & 1) * 128 * VSTR;
            float* xd = Xb0 + ((t + 1) & 1) * RPI * VSTR;
            #pragma unroll
            for (int k = 0; k < 8; k++) {
                int idx = k * 128 + tid, j = idx >> 3, seg = idx & 7;
                cp16(vd + j * VSTR + seg * 4, v0 + (size_t)j * INF_ + i0 + seg * 4);
            }
            cp16(xd + sr * VSTR + ss * 4, xrow0 + i0 + ss * 4);
            cp16(xd + (sr + 16) * VSTR + ss * 4, xrow1 + i0 + ss * 4);
            CP_COMMIT();
            CP_WAIT(1);
        } else {
            CP_WAIT(0);
        }
        __syncthreads();

        #pragma unroll
        for (int ks = 0; ks < 4; ks++) {
            const int kk = ks * 8;
            unsigned a[2][4];
            #pragma unroll
            for (int mt = 0; mt < 2; mt++) {
                const int rb = mt * 16;
                a[mt][0] = f2tf(Xb[(rb + lr) * VSTR + kk + lc]);
                a[mt][1] = f2tf(Xb[(rb + lr + 8) * VSTR + kk + lc]);
                a[mt][2] = f2tf(Xb[(rb + lr) * VSTR + kk + lc + 4]);
                a[mt][3] = f2tf(Xb[(rb + lr + 8) * VSTR + kk + lc + 4]);
            }
            #pragma unroll
            for (int nt = 0; nt < 4; nt++) {
                const int nn = jb + nt * 8 + lr;
                unsigned b0 = f2tf(Vb[nn * VSTR + kk + lc]);
                unsigned b1 = f2tf(Vb[nn * VSTR + kk + lc + 4]);
                mma_tf32(acc[0][nt], a[0][0], a[0][1], a[0][2], a[0][3], b0, b1);
                mma_tf32(acc[1][nt], a[1][0], a[1][1], a[1][2], a[1][3], b0, b1);
            }
        }
        __syncthreads();
    }

    // g_Tpart layout [row][kq][col] so Tred streams contiguously
    #pragma unroll
    for (int mt = 0; mt < 2; mt++) {
        #pragma unroll
        for (int nt = 0; nt < 4; nt++) {
            const int col = jb + nt * 8 + 2 * lc;
            const int row0 = mt * 16 + lr, row1 = row0 + 8;
            if (row0 < m)
                *(float2*)(g_Tpart + ((size_t)(gbase + row0) * KQ + kq) * SUBF + col)
                    = make_float2(acc[mt][nt][0], acc[mt][nt][1]);
            if (row1 < m)
                *(float2*)(g_Tpart + ((size_t)(gbase + row1) * KQ + kq) * SUBF + col)
                    = make_float2(acc[mt][nt][2], acc[mt][nt][3]);
        }
    }
}

// ---------------- kernel Tred: sum 8 contiguous k-partials, apply weight ----------
// Per thread: 8 float4 loads spanning one 4KB block (sequential streaming).
__global__ void __launch_bounds__(256) colak_Tred() {
    const int idx = blockIdx.x * 256 + threadIdx.x;   // 0..65535
    const int row = idx >> 5, qd = idx & 31;
    const float4* base = (const float4*)g_Tpart + (size_t)row * KQ * 32 + qd;

    float4 t0 = base[0];
    float4 t1 = base[32];
    float4 t2 = base[64];
    float4 t3 = base[96];
    float4 t4 = base[128];
    float4 t5 = base[160];
    float4 t6 = base[192];
    float4 t7 = base[224];

    float4 s = f4add(f4add(f4add(t0, t1), f4add(t2, t3)),
                     f4add(f4add(t4, t5), f4add(t6, t7)));
    const float wt = g_asg_w[row];
    s.x *= wt; s.y *= wt; s.z *= wt; s.w *= wt;
    *((float4*)g_T + (size_t)row * 32 + qd) = s;
}

// ---------------- kernel O: stage 2 via tf32 mma (M=32 per CTA) --------------------
// CTA = (32 asg rows, 128-wide o-tile). Same structure as colak_T,
// A = T rows (K=128 j), B = V1 o-rows.
__global__ void __launch_bounds__(128) colak_O(const float* __restrict__ V1) {
    if ((int)blockIdx.x >= g_nwork) return;
    const int item = g_work[blockIdx.x];
    const int s  = item >> 8;
    const int c  = item & 255;
    const int ot = blockIdx.y;            // 0..7
    const int n  = g_cnt[s];
    const int m  = min(RPI, n - c * RPI);
    const int gbase = g_off[s] + c * RPI;

    extern __shared__ float smem[];
    float* Vb0 = smem;                    // 2 x [128][VSTR]
    float* Tb0 = smem + 2 * 128 * VSTR;   // 2 x [32][VSTR]

    const int tid  = threadIdx.x;
    const int w    = tid >> 5;
    const int lane = tid & 31;
    const int lr   = lane >> 2;
    const int lc   = lane & 3;
    const int ob   = w * 32;

    const float* v1 = V1 + (size_t)s * OUTF * SUBF + (size_t)ot * 128 * SUBF;
    const float* tsrc = g_T + (size_t)gbase * SUBF;
    const int sr = tid >> 3, ss = tid & 7;

    // prefetch tile 0 (j0 = 0)
    {
        #pragma unroll
        for (int k = 0; k < 8; k++) {
            int idx = k * 128 + tid, o = idx >> 3, seg = idx & 7;
            cp16(Vb0 + o * VSTR + seg * 4, v1 + (size_t)o * SUBF + seg * 4);
        }
        cp16(Tb0 + sr * VSTR + ss * 4, tsrc + (size_t)sr * SUBF + ss * 4);
        cp16(Tb0 + (sr + 16) * VSTR + ss * 4, tsrc + (size_t)(sr + 16) * SUBF + ss * 4);
        CP_COMMIT();
    }

    float acc[2][4][4];
    #pragma unroll
    for (int mt = 0; mt < 2; mt++)
        #pragma unroll
        for (int nt = 0; nt < 4; nt++)
            #pragma unroll
            for (int i = 0; i < 4; i++) acc[mt][nt][i] = 0.f;

    for (int t = 0; t < 4; t++) {
        const float* Vb = Vb0 + (t & 1) * 128 * VSTR;
        const float* Tb = Tb0 + (t & 1) * RPI * VSTR;
        if (t + 1 < 4) {
            const int j0 = (t + 1) * 32;
            float* vd = Vb0 + ((t + 1) & 1) * 128 * VSTR;
            float* td = Tb0 + ((t + 1) & 1) * RPI * VSTR;
            #pragma unroll
            for (int k = 0; k < 8; k++) {
                int idx = k * 128 + tid, o = idx >> 3, seg = idx & 7;
                cp16(vd + o * VSTR + seg * 4, v1 + (size_t)o * SUBF + j0 + seg * 4);
            }
            cp16(td + sr * VSTR + ss * 4, tsrc + (size_t)sr * SUBF + j0 + ss * 4);
            cp16(td + (sr + 16) * VSTR + ss * 4,
                 tsrc + (size_t)(sr + 16) * SUBF + j0 + ss * 4);
            CP_COMMIT();
            CP_WAIT(1);
        } else {
            CP_WAIT(0);
        }
        __syncthreads();

        #pragma unroll
        for (int ks = 0; ks < 4; ks++) {
            const int kk = ks * 8;
            unsigned a[2][4];
            #pragma unroll
            for (int mt = 0; mt < 2; mt++) {
                const int rb = mt * 16;
                a[mt][0] = f2tf(Tb[(rb + lr) * VSTR + kk + lc]);
                a[mt][1] = f2tf(Tb[(rb + lr + 8) * VSTR + kk + lc]);
                a[mt][2] = f2tf(Tb[(rb + lr) * VSTR + kk + lc + 4]);
                a[mt][3] = f2tf(Tb[(rb + lr + 8) * VSTR + kk + lc + 4]);
            }
            #pragma unroll
            for (int nt = 0; nt < 4; nt++) {
                const int nn = ob + nt * 8 + lr;
                unsigned b0 = f2tf(Vb[nn * VSTR + kk + lc]);
                unsigned b1 = f2tf(Vb[nn * VSTR + kk + lc + 4]);
                mma_tf32(acc[0][nt], a[0][0], a[0][1], a[0][2], a[0][3], b0, b1);
                mma_tf32(acc[1][nt], a[1][0], a[1][1], a[1][2], a[1][3], b0, b1);
            }
        }
        __syncthreads();
    }

    #pragma unroll
    for (int mt = 0; mt < 2; mt++) {
        #pragma unroll
        for (int nt = 0; nt < 4; nt++) {
            const int col = ot * 128 + ob + nt * 8 + 2 * lc;
            const int row0 = mt * 16 + lr, row1 = row0 + 8;
            if (row0 < m)
                *(float2*)(g_opart + (size_t)(gbase + row0) * OUTF + col)
                    = make_float2(acc[mt][nt][0], acc[mt][nt][1]);
            if (row1 < m)
                *(float2*)(g_opart + (size_t)(gbase + row1) * OUTF + col)
                    = make_float2(acc[mt][nt][2], acc[mt][nt][3]);
        }
    }
}

// ---------------- kernel 4: reduce 8 partials per batch row (MLP=8) ---------------
__global__ void __launch_bounds__(256) colak_reduce(float* __restrict__ out) {
    __shared__ int mp[KACT];
    const int b = blockIdx.x;
    const int tid = threadIdx.x;
    if (tid < KACT) mp[tid] = g_map[b * KACT + tid];
    __syncthreads();
    const float4* op = (const float4*)g_opart;

    float4 t0 = op[(size_t)mp[0] * (OUTF / 4) + tid];
    float4 t1 = op[(size_t)mp[1] * (OUTF / 4) + tid];
    float4 t2 = op[(size_t)mp[2] * (OUTF / 4) + tid];
    float4 t3 = op[(size_t)mp[3] * (OUTF / 4) + tid];
    float4 t4 = op[(size_t)mp[4] * (OUTF / 4) + tid];
    float4 t5 = op[(size_t)mp[5] * (OUTF / 4) + tid];
    float4 t6 = op[(size_t)mp[6] * (OUTF / 4) + tid];
    float4 t7 = op[(size_t)mp[7] * (OUTF / 4) + tid];

    float4 s = f4add(f4add(f4add(t0, t1), f4add(t2, t3)),
                     f4add(f4add(t4, t5), f4add(t6, t7)));
    ((float4*)out)[(size_t)b * (OUTF / 4) + tid] = s;
}

// ---------------- host launcher ----------------------------------------------------
extern "C" void kernel_launch(void* const* d_in, const int* in_sizes, int n_in,
                              void* d_out, int out_size) {
    const float* x  = (const float*)d_in[0];
    const float* q  = (const float*)d_in[1];
    const float* Wk = (const float*)d_in[2];
    const float* bk = (const float*)d_in[3];
    const float* V0 = (const float*)d_in[4];
    const float* V1 = (const float*)d_in[5];
    float* out = (float*)d_out;

    colak_attn<<<NB / 4, 256>>>(q, Wk, bk);
    colak_scatter<<<1, 256>>>();
    colak_T<<<dim3(MAXITEMS, KQ), 128, SMEM_MMA_BYTES>>>(x, V0);
    colak_Tred<<<NASG * SUBF / (256 * 4), 256>>>();
    colak_O<<<dim3(MAXITEMS, 8), 128, SMEM_MMA_BYTES>>>(V1);
    colak_reduce<<<NB, 256>>>(out);
}